// round 2
// baseline (speedup 1.0000x reference)
#include <cuda_runtime.h>

// LIF recurrence: v = alpha*v + beta*c; spike = (v >= 1); v = spike ? 0 : v.
// Sequential over T=2048, parallel over N=32768.
// Output: out[0 : T*N] = spikes, out[T*N : 2*T*N] = post-reset voltages.
//
// Purely HBM-bound (768 MB mandatory traffic). Design: 1 thread/neuron,
// 8-deep software-pipelined prefetch of the current stream to get enough
// memory-level parallelism out of only 1024 warps.

#define T_STEPS 2048
#define N_NEUR  32768
#define PF      8          // prefetch/pipeline depth (steps)

__global__ void __launch_bounds__(128, 2)
lif_kernel(const float* __restrict__ cur,
           const float* __restrict__ v0,
           float* __restrict__ out)
{
    const int n = blockIdx.x * blockDim.x + threadIdx.x;

    // Match reference f32 constants: alpha = f32(exp(-1/20)), beta = f32(1 - exp(-1/20))
    const float alpha = (float)0.9512294245007140;
    const float beta  = (float)(1.0 - 0.9512294245007140);

    float v = v0[n];

    const float* cp = cur + n;
    float* sp = out + n;                                  // spikes
    float* vp = out + (size_t)T_STEPS * N_NEUR + n;       // voltages

    // Prime the pipeline with steps 0..PF-1
    float buf[PF];
#pragma unroll
    for (int i = 0; i < PF; ++i)
        buf[i] = cp[(size_t)i * N_NEUR];
    cp += (size_t)PF * N_NEUR;

    // Main loop: issue next PF loads (front-batched by ptxas -> MLP=8),
    // then compute/store the current PF steps.
    for (int t = 0; t < T_STEPS - PF; t += PF) {
        float nxt[PF];
#pragma unroll
        for (int i = 0; i < PF; ++i)
            nxt[i] = cp[(size_t)i * N_NEUR];
        cp += (size_t)PF * N_NEUR;

#pragma unroll
        for (int i = 0; i < PF; ++i) {
            // v = alpha*v + beta*c, explicitly unfused to match reference rounding
            v = __fadd_rn(__fmul_rn(alpha, v), __fmul_rn(beta, buf[i]));
            const bool fire = (v >= 1.0f);
            const float s = fire ? 1.0f : 0.0f;
            v = fire ? 0.0f : v;
            *sp = s;
            *vp = v;
            sp += N_NEUR;
            vp += N_NEUR;
        }

#pragma unroll
        for (int i = 0; i < PF; ++i)
            buf[i] = nxt[i];
    }

    // Drain the final PF steps
#pragma unroll
    for (int i = 0; i < PF; ++i) {
        v = __fadd_rn(__fmul_rn(alpha, v), __fmul_rn(beta, buf[i]));
        const bool fire = (v >= 1.0f);
        const float s = fire ? 1.0f : 0.0f;
        v = fire ? 0.0f : v;
        *sp = s;
        *vp = v;
        sp += N_NEUR;
        vp += N_NEUR;
    }
}

extern "C" void kernel_launch(void* const* d_in, const int* in_sizes, int n_in,
                              void* d_out, int out_size)
{
    const float* currents = (const float*)d_in[0];   // (T, N) float32
    const float* v0       = (const float*)d_in[1];   // (N,)  float32
    float* out            = (float*)d_out;           // 2*T*N float32

    lif_kernel<<<N_NEUR / 128, 128>>>(currents, v0, out);
}